// round 3
// baseline (speedup 1.0000x reference)
#include <cuda_runtime.h>
#include <cstdint>

// Problem constants
#define B 8
#define C 256
#define C2 256
#define H 64
#define W 64
#define KK 9
#define MAXOFF 16.0f

// Scratch (device globals; no dynamic allocation allowed)
__device__ float  g_om[B * 27 * H * W];          // offset(0..17) + mask(18..26) per (b,o,h,w)
__device__ int4   g_didx[B * H * KK * W];        // [(b*64+h)*576 + k*64 + w] clamped corner indices
__device__ float4 g_dw[B * H * KK * W];          // corner weights * mask * validity
__device__ float  g_wT[2304 * 256];              // reg_w transposed: [r=c*9+k][oc]

// ---------------------------------------------------------------------------
// Kernel 0: transpose reg_w[oc][c][ky][kx] -> g_wT[r][oc]
// ---------------------------------------------------------------------------
__global__ void k_transpose_w(const float* __restrict__ reg_w) {
    int t = blockIdx.x * blockDim.x + threadIdx.x;  // over 2304*256
    if (t >= 2304 * 256) return;
    int oc = t & 255;
    int r  = t >> 8;
    g_wT[r * 256 + oc] = reg_w[oc * 2304 + r];
}

// ---------------------------------------------------------------------------
// Kernel 1: 27-channel 3x3 conv (offset 18ch clipped, modulator 9ch sigmoid)
// One block per (b,h) row. 256 threads: tx=tid&15 -> 4 pixels, ty=tid>>4 -> outs {ty, ty+16}
// ---------------------------------------------------------------------------
__global__ void __launch_bounds__(256) k_conv_om(
    const float* __restrict__ x,
    const float* __restrict__ ow, const float* __restrict__ ob,
    const float* __restrict__ mw, const float* __restrict__ mb)
{
    __shared__ float xs[16 * 3 * 72];   // 16 ch x 3 rows x (66 cols padded to 72)
    __shared__ float w1[144 * 28];      // 144 r-rows x 27 outs (pad 28)

    const int bh = blockIdx.x;
    const int b = bh >> 6, h = bh & 63;
    const int tid = threadIdx.x;
    const int tx = tid & 15, ty = tid >> 4;

    float acc0[4] = {0.f, 0.f, 0.f, 0.f};
    float acc1[4] = {0.f, 0.f, 0.f, 0.f};

    for (int c0 = 0; c0 < C; c0 += 16) {
        // stage x tile: 16 ch x 3 rows x 66 cols (col 0 <-> w=-1)
        for (int u = tid; u < 16 * 3 * 66; u += 256) {
            int cc = u / 198, r2 = u % 198;
            int ry = r2 / 66, col = r2 % 66;
            int y = h - 1 + ry, xw = col - 1;
            float v = 0.f;
            if (y >= 0 && y < H && xw >= 0 && xw < W)
                v = x[((b * C + c0 + cc) * H + y) * W + xw];
            xs[(cc * 3 + ry) * 72 + col] = v;
        }
        // stage weights: w1[rr][o], rr = cc*9 + ky*3 + kx
        for (int u = tid; u < 144 * 27; u += 256) {
            int rr = u / 27, o = u % 27;
            int cc = rr / 9, kk = rr % 9;
            float v;
            if (o < 18) v = ow[(o * C + c0 + cc) * 9 + kk];
            else        v = mw[((o - 18) * C + c0 + cc) * 9 + kk];
            w1[rr * 28 + o] = v;
        }
        __syncthreads();

        #pragma unroll 4
        for (int cc = 0; cc < 16; cc++) {
            #pragma unroll
            for (int ky = 0; ky < 3; ky++) {
                const float* row = &xs[(cc * 3 + ky) * 72 + tx * 4];
                float4 a4 = *(const float4*)row;
                float2 b2 = *(const float2*)(row + 4);
                float xr[6] = {a4.x, a4.y, a4.z, a4.w, b2.x, b2.y};
                #pragma unroll
                for (int kx = 0; kx < 3; kx++) {
                    int r = cc * 9 + ky * 3 + kx;
                    float wa = w1[r * 28 + ty];
                    float wb = (ty < 11) ? w1[r * 28 + ty + 16] : 0.f;
                    #pragma unroll
                    for (int ii = 0; ii < 4; ii++) {
                        acc0[ii] = fmaf(wa, xr[ii + kx], acc0[ii]);
                        acc1[ii] = fmaf(wb, xr[ii + kx], acc1[ii]);
                    }
                }
            }
        }
        __syncthreads();
    }

    // epilogue: bias + clip / sigmoid, write g_om
    {
        int o = ty;
        float bia = (o < 18) ? ob[o] : mb[o - 18];
        #pragma unroll
        for (int ii = 0; ii < 4; ii++) {
            float v = acc0[ii] + bia;
            if (o < 18) v = fminf(fmaxf(v, -MAXOFF), MAXOFF);
            else        v = 1.f / (1.f + expf(-v));
            g_om[(b * 27 + o) * (H * W) + h * W + tx * 4 + ii] = v;
        }
    }
    if (ty < 11) {
        int o = ty + 16;
        float bia = (o < 18) ? ob[o] : mb[o - 18];
        #pragma unroll
        for (int ii = 0; ii < 4; ii++) {
            float v = acc1[ii] + bia;
            if (o < 18) v = fminf(fmaxf(v, -MAXOFF), MAXOFF);
            else        v = 1.f / (1.f + expf(-v));
            g_om[(b * 27 + o) * (H * W) + h * W + tx * 4 + ii] = v;
        }
    }
}

// ---------------------------------------------------------------------------
// Kernel 2: build bilinear sampling descriptors per (b,h,k,w)
// ---------------------------------------------------------------------------
__global__ void k_build_desc() {
    int t = blockIdx.x * blockDim.x + threadIdx.x;   // over B*H*KK*W = 294912
    if (t >= B * H * KK * W) return;
    int w = t & 63;
    int k = (t >> 6) % 9;
    int bh = t / 576;
    int h = bh & 63, b = bh >> 6;

    const int hw = h * W + w;
    float dy = g_om[(b * 27 + 2 * k) * (H * W) + hw];
    float dx = g_om[(b * 27 + 2 * k + 1) * (H * W) + hw];
    float m  = g_om[(b * 27 + 18 + k) * (H * W) + hw];

    int ky = k / 3, kx = k % 3;
    float py = (float)(h - 1 + ky) + dy;
    float px = (float)(w - 1 + kx) + dx;
    float y0f = floorf(py), x0f = floorf(px);
    float ly = py - y0f, lx = px - x0f;
    int y0 = (int)y0f, x0 = (int)x0f;
    int y1 = y0 + 1, x1 = x0 + 1;

    float v00 = (y0 >= 0 && y0 < H && x0 >= 0 && x0 < W) ? 1.f : 0.f;
    float v01 = (y0 >= 0 && y0 < H && x1 >= 0 && x1 < W) ? 1.f : 0.f;
    float v10 = (y1 >= 0 && y1 < H && x0 >= 0 && x0 < W) ? 1.f : 0.f;
    float v11 = (y1 >= 0 && y1 < H && x1 >= 0 && x1 < W) ? 1.f : 0.f;

    int cy0 = min(max(y0, 0), H - 1), cy1 = min(max(y1, 0), H - 1);
    int cx0 = min(max(x0, 0), W - 1), cx1 = min(max(x1, 0), W - 1);

    int4 di;
    di.x = cy0 * W + cx0;
    di.y = cy0 * W + cx1;
    di.z = cy1 * W + cx0;
    di.w = cy1 * W + cx1;

    float4 dw;
    dw.x = (1.f - ly) * (1.f - lx) * m * v00;
    dw.y = (1.f - ly) * lx * m * v01;
    dw.z = ly * (1.f - lx) * m * v10;
    dw.w = ly * lx * m * v11;

    g_didx[t] = di;
    g_dw[t] = dw;
}

// ---------------------------------------------------------------------------
// Kernel 3: main deformable contraction.
// One block per (b,h): tile = 64 pixels x 256 output channels.
// Reduction r = c*9+k in chunks of 72 (8 channels x 9 taps).
// Sampled values generated on the fly into smem; weights staged from g_wT.
// Thread map: tx=tid&15 -> pixels tx*4..+3 ; ty=tid>>4 -> oc ty*16..+15.
// ---------------------------------------------------------------------------
#define RCHUNK 72
#define SMEM_K3 (576*16 + 576*16 + RCHUNK*64*4 + RCHUNK*256*4)   // 110592 B

__global__ void __launch_bounds__(256) k_dconv_main(
    const float* __restrict__ x, float* __restrict__ out)
{
    extern __shared__ float smem[];
    int4*   s_idx = (int4*)smem;                       // 576
    float4* s_w   = (float4*)(s_idx + 576);            // 576
    float*  sv    = (float*)(s_w + 576);               // [72][64]
    float*  wsm   = sv + RCHUNK * 64;                  // [72][256]

    const int bh = blockIdx.x;
    const int b = bh >> 6, h = bh & 63;
    const int tid = threadIdx.x;
    const int tx = tid & 15, ty = tid >> 4;

    // stage descriptors for this (b,h): 576 taps*pixels
    for (int u = tid; u < 576; u += 256) {
        s_idx[u] = g_didx[bh * 576 + u];
        s_w[u]   = g_dw[bh * 576 + u];
    }

    float4 acc4[16];
    #pragma unroll
    for (int i = 0; i < 16; i++) acc4[i] = make_float4(0.f, 0.f, 0.f, 0.f);

    const float* xb_base = x + b * C * (H * W);

    for (int c0 = 0; c0 < C; c0 += 8) {
        __syncthreads();   // protect smem from previous chunk's compute

        // stage weights: g_wT rows [c0*9 .. c0*9+72) x 256  (coalesced float4 copy)
        {
            const float4* wg = (const float4*)(g_wT + c0 * 9 * 256);
            float4* ws4 = (float4*)wsm;
            #pragma unroll
            for (int i = 0; i < 18; i++)
                ws4[tid + 256 * i] = wg[tid + 256 * i];
        }
        // generate sampled values: sv[rr][p], rr = c_local*9 + k
        #pragma unroll
        for (int i = 0; i < 18; i++) {
            int v = tid + 256 * i;
            int rr = v >> 6, p = v & 63;
            int cl = rr / 9, k = rr - cl * 9;
            int d = k * 64 + p;
            int4 di = s_idx[d];
            float4 dwv = s_w[d];
            const float* xb = xb_base + (c0 + cl) * (H * W);
            float val = dwv.x * __ldg(&xb[di.x]) + dwv.y * __ldg(&xb[di.y])
                      + dwv.z * __ldg(&xb[di.z]) + dwv.w * __ldg(&xb[di.w]);
            sv[rr * 64 + p] = val;
        }
        __syncthreads();

        // FMA mainloop: 72 reduction rows x (16 oc x 4 px) per thread
        const float4* svq = (const float4*)sv;    // [72][16]
        const float4* wq  = (const float4*)wsm;   // [72][64]
        #pragma unroll 2
        for (int rr = 0; rr < RCHUNK; rr++) {
            float4 s = svq[rr * 16 + tx];
            #pragma unroll
            for (int j = 0; j < 4; j++) {
                float4 wv = wq[rr * 64 + ty * 4 + j];
                acc4[j*4+0].x = fmaf(wv.x, s.x, acc4[j*4+0].x);
                acc4[j*4+0].y = fmaf(wv.x, s.y, acc4[j*4+0].y);
                acc4[j*4+0].z = fmaf(wv.x, s.z, acc4[j*4+0].z);
                acc4[j*4+0].w = fmaf(wv.x, s.w, acc4[j*4+0].w);
                acc4[j*4+1].x = fmaf(wv.y, s.x, acc4[j*4+1].x);
                acc4[j*4+1].y = fmaf(wv.y, s.y, acc4[j*4+1].y);
                acc4[j*4+1].z = fmaf(wv.y, s.z, acc4[j*4+1].z);
                acc4[j*4+1].w = fmaf(wv.y, s.w, acc4[j*4+1].w);
                acc4[j*4+2].x = fmaf(wv.z, s.x, acc4[j*4+2].x);
                acc4[j*4+2].y = fmaf(wv.z, s.y, acc4[j*4+2].y);
                acc4[j*4+2].z = fmaf(wv.z, s.z, acc4[j*4+2].z);
                acc4[j*4+2].w = fmaf(wv.z, s.w, acc4[j*4+2].w);
                acc4[j*4+3].x = fmaf(wv.w, s.x, acc4[j*4+3].x);
                acc4[j*4+3].y = fmaf(wv.w, s.y, acc4[j*4+3].y);
                acc4[j*4+3].z = fmaf(wv.w, s.z, acc4[j*4+3].z);
                acc4[j*4+3].w = fmaf(wv.w, s.w, acc4[j*4+3].w);
            }
        }
    }

    // epilogue: out[b][oc][h][tx*4..+3]
    #pragma unroll
    for (int j = 0; j < 4; j++) {
        #pragma unroll
        for (int jj = 0; jj < 4; jj++) {
            int oc = ty * 16 + j * 4 + jj;
            *(float4*)&out[((b * C2 + oc) * H + h) * W + tx * 4] = acc4[j * 4 + jj];
        }
    }
}

// ---------------------------------------------------------------------------
extern "C" void kernel_launch(void* const* d_in, const int* in_sizes, int n_in,
                              void* d_out, int out_size) {
    const float* x    = (const float*)d_in[0];
    const float* ow   = (const float*)d_in[1];
    const float* ob   = (const float*)d_in[2];
    const float* mw   = (const float*)d_in[3];
    const float* mb   = (const float*)d_in[4];
    const float* regw = (const float*)d_in[5];
    float* out = (float*)d_out;

    (void)in_sizes; (void)n_in; (void)out_size;

    cudaFuncSetAttribute(k_dconv_main, cudaFuncAttributeMaxDynamicSharedMemorySize, SMEM_K3);

    k_transpose_w<<<(2304 * 256) / 256, 256>>>(regw);
    k_conv_om<<<B * H, 256>>>(x, ow, ob, mw, mb);
    k_build_desc<<<(B * H * KK * W + 255) / 256, 256>>>();
    k_dconv_main<<<B * H, 256, SMEM_K3>>>(x, out);
}

// round 8
// speedup vs baseline: 2.9822x; 2.9822x over previous
#include <cuda_runtime.h>
#include <cuda_bf16.h>
#include <cstdint>

#define B 8
#define C 256
#define H 64
#define W 64
#define MAXOFF 16.0f
#define NCH 36                       // K chunks of 64 over K=2304

__device__ float  g_om[B * 27 * H * W];
__device__ int4   g_didx[B * H * 9 * W];
__device__ float4 g_dw[B * H * 9 * W];
__device__ uint4  g_wpack[2 * NCH * 2048];   // [half][chunk][oc][kq] bf16 weights

// ---- PTX helpers (all plain-sm_103-legal: ldmatrix sm_75+, mma bf16 sm_80+) ----
__device__ __forceinline__ uint32_t smem_u32(const void* p) {
    uint32_t a;
    asm("{ .reg .u64 t; cvta.to.shared.u64 t, %1; cvt.u32.u64 %0, t; }" : "=r"(a) : "l"(p));
    return a;
}
#define LDM4(r, addr) \
    asm volatile("ldmatrix.sync.aligned.m8n8.x4.shared.b16 {%0,%1,%2,%3}, [%4];" \
        : "=r"((r)[0]), "=r"((r)[1]), "=r"((r)[2]), "=r"((r)[3]) : "r"(addr))
#define MMA(acc, a, b0, b1) \
    asm volatile("mma.sync.aligned.m16n8k16.row.col.f32.bf16.bf16.f32 " \
        "{%0,%1,%2,%3}, {%4,%5,%6,%7}, {%8,%9}, {%0,%1,%2,%3};" \
        : "+f"((acc)[0]), "+f"((acc)[1]), "+f"((acc)[2]), "+f"((acc)[3]) \
        : "r"((a)[0]), "r"((a)[1]), "r"((a)[2]), "r"((a)[3]), "r"(b0), "r"(b1))

// ---- prep: pack reg_w -> bf16 hi/lo, layout [half][chunk][oc][k] ----------
__global__ void k_prep(const float* __restrict__ reg_w) {
    int t = blockIdx.x * blockDim.x + threadIdx.x;
    if (t >= 2 * NCH * 2048) return;
    int u = t & 2047, chunk = (t >> 11) % NCH, half = t / (NCH * 2048);
    int oc = u >> 3, col = (u & 7) * 8;
    unsigned short s[8];
#pragma unroll
    for (int e = 0; e < 8; e++) {
        float wv = reg_w[oc * 2304 + chunk * 64 + col + e];
        __nv_bfloat16 hi = __float2bfloat16(wv);
        __nv_bfloat16 o = half ? __float2bfloat16(wv - __bfloat162float(hi)) : hi;
        s[e] = *reinterpret_cast<unsigned short*>(&o);
    }
    uint4 v;
    v.x = s[0] | ((unsigned)s[1] << 16); v.y = s[2] | ((unsigned)s[3] << 16);
    v.z = s[4] | ((unsigned)s[5] << 16); v.w = s[6] | ((unsigned)s[7] << 16);
    g_wpack[t] = v;
}

// ---- 27-ch 3x3 conv (unchanged) ------------------------------------------
__global__ void __launch_bounds__(256) k_conv_om(
    const float* __restrict__ x, const float* __restrict__ ow, const float* __restrict__ ob,
    const float* __restrict__ mw, const float* __restrict__ mb)
{
    __shared__ float xs[16 * 3 * 72];
    __shared__ float w1[144 * 28];
    const int bh = blockIdx.x, b = bh >> 6, h = bh & 63;
    const int tid = threadIdx.x, tx = tid & 15, ty = tid >> 4;
    float acc0[4] = {0,0,0,0}, acc1[4] = {0,0,0,0};

    for (int c0 = 0; c0 < C; c0 += 16) {
        for (int u = tid; u < 16 * 3 * 66; u += 256) {
            int cc = u / 198, r2 = u % 198, ry = r2 / 66, col = r2 % 66;
            int y = h - 1 + ry, xw = col - 1;
            float v = 0.f;
            if (y >= 0 && y < H && xw >= 0 && xw < W) v = x[((b * C + c0 + cc) * H + y) * W + xw];
            xs[(cc * 3 + ry) * 72 + col] = v;
        }
        for (int u = tid; u < 144 * 27; u += 256) {
            int rr = u / 27, o = u % 27, cc = rr / 9, kk = rr % 9;
            w1[rr * 28 + o] = (o < 18) ? ow[(o * C + c0 + cc) * 9 + kk] : mw[((o - 18) * C + c0 + cc) * 9 + kk];
        }
        __syncthreads();
#pragma unroll 4
        for (int cc = 0; cc < 16; cc++)
#pragma unroll
            for (int ky = 0; ky < 3; ky++) {
                const float* row = &xs[(cc * 3 + ky) * 72 + tx * 4];
                float4 a4 = *(const float4*)row;
                float2 b2 = *(const float2*)(row + 4);
                float xr[6] = {a4.x, a4.y, a4.z, a4.w, b2.x, b2.y};
#pragma unroll
                for (int kx = 0; kx < 3; kx++) {
                    int r = cc * 9 + ky * 3 + kx;
                    float wa = w1[r * 28 + ty];
                    float wb = (ty < 11) ? w1[r * 28 + ty + 16] : 0.f;
#pragma unroll
                    for (int ii = 0; ii < 4; ii++) {
                        acc0[ii] = fmaf(wa, xr[ii + kx], acc0[ii]);
                        acc1[ii] = fmaf(wb, xr[ii + kx], acc1[ii]);
                    }
                }
            }
        __syncthreads();
    }
    {
        int o = ty; float bia = (o < 18) ? ob[o] : mb[o - 18];
#pragma unroll
        for (int ii = 0; ii < 4; ii++) {
            float v = acc0[ii] + bia;
            v = (o < 18) ? fminf(fmaxf(v, -MAXOFF), MAXOFF) : 1.f / (1.f + expf(-v));
            g_om[(b * 27 + o) * (H * W) + h * W + tx * 4 + ii] = v;
        }
    }
    if (ty < 11) {
        int o = ty + 16; float bia = (o < 18) ? ob[o] : mb[o - 18];
#pragma unroll
        for (int ii = 0; ii < 4; ii++) {
            float v = acc1[ii] + bia;
            v = (o < 18) ? fminf(fmaxf(v, -MAXOFF), MAXOFF) : 1.f / (1.f + expf(-v));
            g_om[(b * 27 + o) * (H * W) + h * W + tx * 4 + ii] = v;
        }
    }
}

// ---- bilinear descriptors (unchanged) ------------------------------------
__global__ void k_build_desc() {
    int t = blockIdx.x * blockDim.x + threadIdx.x;
    if (t >= B * H * 9 * W) return;
    int w = t & 63, k = (t >> 6) % 9, bh = t / 576, h = bh & 63, b = bh >> 6;
    const int hw = h * W + w;
    float dy = g_om[(b * 27 + 2 * k) * (H * W) + hw];
    float dx = g_om[(b * 27 + 2 * k + 1) * (H * W) + hw];
    float m  = g_om[(b * 27 + 18 + k) * (H * W) + hw];
    float py = (float)(h - 1 + k / 3) + dy, px = (float)(w - 1 + k % 3) + dx;
    float y0f = floorf(py), x0f = floorf(px);
    float ly = py - y0f, lx = px - x0f;
    int y0 = (int)y0f, x0 = (int)x0f, y1 = y0 + 1, x1 = x0 + 1;
    float v00 = (y0 >= 0 && y0 < H && x0 >= 0 && x0 < W) ? 1.f : 0.f;
    float v01 = (y0 >= 0 && y0 < H && x1 >= 0 && x1 < W) ? 1.f : 0.f;
    float v10 = (y1 >= 0 && y1 < H && x0 >= 0 && x0 < W) ? 1.f : 0.f;
    float v11 = (y1 >= 0 && y1 < H && x1 >= 0 && x1 < W) ? 1.f : 0.f;
    int cy0 = min(max(y0, 0), H - 1), cy1 = min(max(y1, 0), H - 1);
    int cx0 = min(max(x0, 0), W - 1), cx1 = min(max(x1, 0), W - 1);
    g_didx[t] = make_int4(cy0 * W + cx0, cy0 * W + cx1, cy1 * W + cx0, cy1 * W + cx1);
    g_dw[t] = make_float4((1.f - ly) * (1.f - lx) * m * v00, (1.f - ly) * lx * m * v01,
                          ly * (1.f - lx) * m * v10, ly * lx * m * v11);
}

// ---- main: mma.sync bf16 3-pass GEMM, M=128 px, N=256 oc, K=2304 ---------
// smem rows padded to 144B (72 bf16): conflict-free ldmatrix, k in [0,64)
// Ahi @0 (18432) | Alo @18432 | Bhi @36864 (36864) | Blo @73728
// s_idx @110592 (18432) | s_wt @129024 (18432)  => total 147456
#define SMEM_MM 147456
__global__ void __launch_bounds__(256, 1) k_dconv_mma(const float* __restrict__ x, float* __restrict__ out) {
    extern __shared__ char sm[];
    char* Ahi = sm;            char* Alo = sm + 18432;
    char* Bhi = sm + 36864;    char* Blo = sm + 73728;
    int4*   s_idx = (int4*)(sm + 110592);
    float4* s_wt  = (float4*)(sm + 129024);

    const int tid = threadIdx.x, wid = tid >> 5, lid = tid & 31;
    const int b = blockIdx.x >> 5, h0 = (blockIdx.x & 31) * 2;
    const int m0 = (wid & 3) * 32;       // warp M origin (px)
    const int n0 = (wid >> 2) * 128;     // warp N origin (oc)

    // stage descriptors: 1152 = 2 rows x 9 taps x 64 px
    for (int u = tid; u < 1152; u += 256) {
        int g = (b * 64 + h0 + (u >= 576)) * 576 + (u >= 576 ? u - 576 : u);
        s_idx[u] = g_didx[g];
        s_wt[u]  = g_dw[g];
    }

    // per-lane ldmatrix base addresses
    const uint32_t aHb = smem_u32(Ahi) + (m0 + (lid & 15)) * 144 + (lid >> 4) * 16;
    const uint32_t aLb = aHb + 18432;
    const uint32_t bHb = smem_u32(Bhi) + (n0 + (lid & 7) + ((lid >> 4) << 3)) * 144 + ((lid >> 3) & 1) * 16;
    const uint32_t bLb = bHb + 36864;

    float acc[2][16][4];
#pragma unroll
    for (int i = 0; i < 2; i++)
#pragma unroll
        for (int j = 0; j < 16; j++) {
            acc[i][j][0] = 0.f; acc[i][j][1] = 0.f; acc[i][j][2] = 0.f; acc[i][j][3] = 0.f;
        }

    const int px = tid & 127, hb = tid >> 7;
    const int w = px & 63, h2 = px >> 6;
    const float* xb0 = x + (size_t)b * C * 4096;
    __syncthreads();

    for (int chunk = 0; chunk < NCH; chunk++) {
        // B tiles: [oc][k] rows 144B
        {
            const uint4* bh4 = g_wpack + chunk * 2048;
            const uint4* bl4 = g_wpack + (NCH + chunk) * 2048;
#pragma unroll
            for (int j = 0; j < 8; j++) {
                int u = tid + j * 256;
                uint32_t o = (uint32_t)((u >> 3) * 144 + (u & 7) * 16);
                *(uint4*)(Bhi + o) = bh4[u];
                *(uint4*)(Blo + o) = bl4[u];
            }
        }
        // A tile: sample + hi/lo split; A[px][rr], row 144B
        {
            int bm = chunk % 9;
#pragma unroll
            for (int kk = 0; kk < 9; kk++) {
                int a = kk - bm; if (a < 0) a += 9;
                int rr = ((a ^ hb) & 1) ? a + 9 : a;
                int d = h2 * 576 + kk * 64 + w;
                int4 di = s_idx[d];
                float4 dw = s_wt[d];
                const float* xb = xb0 + (size_t)((chunk * 64 + rr) / 9) * 4096;
                for (; rr < 64; rr += 18, xb += 8192) {
                    float v = dw.x * __ldg(xb + di.x) + dw.y * __ldg(xb + di.y)
                            + dw.z * __ldg(xb + di.z) + dw.w * __ldg(xb + di.w);
                    __nv_bfloat16 hi = __float2bfloat16(v);
                    __nv_bfloat16 lo = __float2bfloat16(v - __bfloat162float(hi));
                    uint32_t o = (uint32_t)(px * 144 + rr * 2);
                    *(__nv_bfloat16*)(Ahi + o) = hi;
                    *(__nv_bfloat16*)(Alo + o) = lo;
                }
            }
        }
        __syncthreads();

        // MMA: 4 k-steps of 16; per step: A frags (2m x hi/lo), B pairs (8 x4-loads x hi/lo)
#pragma unroll
        for (int ks = 0; ks < 4; ks++) {
            uint32_t aH[2][4], aL[2][4];
#pragma unroll
            for (int mm = 0; mm < 2; mm++) {
                LDM4(aH[mm], aHb + mm * 2304 + ks * 32);
                LDM4(aL[mm], aLb + mm * 2304 + ks * 32);
            }
#pragma unroll
            for (int nn2 = 0; nn2 < 8; nn2++) {
                uint32_t bh[4], bl[4];
                LDM4(bh, bHb + nn2 * 2304 + ks * 32);
                LDM4(bl, bLb + nn2 * 2304 + ks * 32);
#pragma unroll
                for (int mm = 0; mm < 2; mm++) {
                    MMA(acc[mm][2 * nn2],     aH[mm], bh[0], bh[1]);
                    MMA(acc[mm][2 * nn2 + 1], aH[mm], bh[2], bh[3]);
                    MMA(acc[mm][2 * nn2],     aL[mm], bh[0], bh[1]);
                    MMA(acc[mm][2 * nn2 + 1], aL[mm], bh[2], bh[3]);
                    MMA(acc[mm][2 * nn2],     aH[mm], bl[0], bl[1]);
                    MMA(acc[mm][2 * nn2 + 1], aH[mm], bl[2], bl[3]);
                }
            }
        }
        __syncthreads();
    }

    // epilogue: c0,c1 = (row g, cols 2tc,2tc+1); c2,c3 = (row g+8, same cols)
    {
        const int g = lid >> 2, tc = lid & 3;
#pragma unroll
        for (int mm = 0; mm < 2; mm++) {
            int px0 = m0 + mm * 16 + g, px1 = px0 + 8;
            size_t i0 = (size_t)(h0 + (px0 >> 6)) * 64 + (px0 & 63);
            size_t i1 = (size_t)(h0 + (px1 >> 6)) * 64 + (px1 & 63);
#pragma unroll
            for (int nn = 0; nn < 16; nn++) {
                int oc = n0 + nn * 8 + 2 * tc;
                size_t r0 = (size_t)(b * 256 + oc) * 4096;
                out[r0 + i0]        = acc[mm][nn][0];
                out[r0 + 4096 + i0] = acc[mm][nn][1];
                out[r0 + i1]        = acc[mm][nn][2];
                out[r0 + 4096 + i1] = acc[mm][nn][3];
            }
        }
    }
}

// ---------------------------------------------------------------------------
extern "C" void kernel_launch(void* const* d_in, const int* in_sizes, int n_in,
                              void* d_out, int out_size) {
    const float* x  = (const float*)d_in[0];
    const float* ow = (const float*)d_in[1];
    const float* ob = (const float*)d_in[2];
    const float* mw = (const float*)d_in[3];
    const float* mb = (const float*)d_in[4];
    const float* rw = (const float*)d_in[5];
    float* out = (float*)d_out;
    (void)in_sizes; (void)n_in; (void)out_size;

    cudaFuncSetAttribute(k_dconv_mma, cudaFuncAttributeMaxDynamicSharedMemorySize, SMEM_MM);
    k_prep<<<(2 * NCH * 2048 + 255) / 256, 256>>>(rw);
    k_conv_om<<<B * H, 256>>>(x, ow, ob, mw, mb);
    k_build_desc<<<(B * H * 9 * W + 255) / 256, 256>>>();
    k_dconv_mma<<<B * (H / 2), 256, SMEM_MM>>>(x, out);
}